// round 6
// baseline (speedup 1.0000x reference)
#include <cuda_runtime.h>
#include <math.h>
#include <stdint.h>
#include <stddef.h>

// ---------------- problem dims ----------------
#define B_    64
#define N_    4096
#define DIN_  256
#define K_    8
#define D_    256
#define H_    512
#define BK_   512
#define SCALE_ 0.0625f
#define EPSLN 1e-5f
#define EPSA  1e-8f

typedef unsigned long long u64;

// ---------------- device scratch ----------------
__device__ __align__(16) float g_slots[BK_ * D_];
__device__ __align__(16) float g_gq[BK_ * D_];      // g ⊙ qt
__device__ float g_C1[BK_];
__device__ float g_C2[BK_];
__device__ __align__(16) float g_P[BK_ * D_];       // Σ a*rs*v
__device__ float g_SA[BK_];
__device__ float g_SW[BK_];
__device__ __align__(16) float g_Wqk[D_ * D_];
__device__ float g_bqk[D_];
__device__ float g_wb[D_];
__device__ float g_c0;
__device__ __align__(16) float g_WihT[D_ * 3 * D_];
__device__ __align__(16) float g_WhhT[D_ * 3 * D_];
__device__ __align__(16) float g_WvT[D_ * D_];
__device__ __align__(16) float g_W1T[D_ * H_];
__device__ __align__(16) float g_W2T[H_ * D_];

// ---------------- f32x2 packed helpers ----------------
__device__ __forceinline__ u64 pk2(float x, float y) {
    u64 r; asm("mov.b64 %0, {%1, %2};" : "=l"(r) : "f"(x), "f"(y)); return r;
}
__device__ __forceinline__ void upk2(u64 v, float& x, float& y) {
    asm("mov.b64 {%0, %1}, %2;" : "=f"(x), "=f"(y) : "l"(v));
}
__device__ __forceinline__ void fma2(u64& d, u64 a, u64 b) {
    asm("fma.rn.f32x2 %0, %1, %2, %0;" : "+l"(d) : "l"(a), "l"(b));
}

// ---------------- block reduce (2 values, 256 threads) ----------------
__device__ __forceinline__ void blockReduce2(float& a, float& b) {
    #pragma unroll
    for (int o = 16; o; o >>= 1) {
        a += __shfl_xor_sync(0xffffffffu, a, o);
        b += __shfl_xor_sync(0xffffffffu, b, o);
    }
    __shared__ float sa[8], sb[8];
    __syncthreads();
    int w = threadIdx.x >> 5;
    if ((threadIdx.x & 31) == 0) { sa[w] = a; sb[w] = b; }
    __syncthreads();
    a = sa[threadIdx.x & 7];
    b = sb[threadIdx.x & 7];
    #pragma unroll
    for (int o = 4; o; o >>= 1) {
        a += __shfl_xor_sync(0xffffffffu, a, o);
        b += __shfl_xor_sync(0xffffffffu, b, o);
    }
}

// =================== SETUP: all transposes + slot init in ONE launch ===================
// grid 1216, block 256.
__device__ __forceinline__ void tTile(const float* __restrict__ src, float* __restrict__ dst,
                                      int R, int C, int bx, int by) {
    __shared__ float t[32][33];
    int tx = threadIdx.x & 31, ty = threadIdx.x >> 5;
    int c = bx * 32 + tx;
    int r = by * 32 + ty;
    #pragma unroll
    for (int k = 0; k < 32; k += 8)
        t[ty + k][tx] = src[(size_t)(r + k) * C + c];
    __syncthreads();
    int cc = bx * 32 + ty;
    int rr = by * 32 + tx;
    #pragma unroll
    for (int k = 0; k < 32; k += 8)
        dst[(size_t)(cc + k) * R + rr] = t[tx][ty + k];
}

__global__ void __launch_bounds__(256) kSetup(const float* __restrict__ W_ih, const float* __restrict__ W_hh,
                                              const float* __restrict__ Wv, const float* __restrict__ W1,
                                              const float* __restrict__ W2, const float* __restrict__ noise,
                                              const float* __restrict__ mu, const float* __restrict__ ls) {
    int t = blockIdx.x;
    if (t < 192)       tTile(W_ih, g_WihT, 768, 256, t & 7, t >> 3);
    else if (t < 384)  { int u = t - 192; tTile(W_hh, g_WhhT, 768, 256, u & 7, u >> 3); }
    else if (t < 448)  { int u = t - 384; tTile(Wv,   g_WvT,  256, 256, u & 7, u >> 3); }
    else if (t < 576)  { int u = t - 448; tTile(W1,   g_W1T,  512, 256, u & 7, u >> 3); }
    else if (t < 704)  { int u = t - 576; tTile(W2,   g_W2T,  256, 512, u & 15, u >> 4); }
    else {
        int idx = (t - 704) * 256 + threadIdx.x;
        int d = idx & 255;
        g_slots[idx] = mu[d] + __expf(ls[d]) * noise[idx];
    }
}

// =================== Wqk + bqk + wb + c0 in ONE launch ===================
// grid 259, block 256.
__global__ void __launch_bounds__(256) kWqkAll(const float* __restrict__ Wq, const float* __restrict__ Wk,
                                               const float* __restrict__ bq, const float* __restrict__ bk) {
    int i = threadIdx.x;
    if (blockIdx.x < 256) {
        int j = blockIdx.x;
        float a0 = 0.f, a1 = 0.f, a2 = 0.f, a3 = 0.f;
        #pragma unroll 4
        for (int d = 0; d < 256; d += 4) {
            a0 = fmaf(Wq[(d + 0) * 256 + j], Wk[(d + 0) * 256 + i], a0);
            a1 = fmaf(Wq[(d + 1) * 256 + j], Wk[(d + 1) * 256 + i], a1);
            a2 = fmaf(Wq[(d + 2) * 256 + j], Wk[(d + 2) * 256 + i], a2);
            a3 = fmaf(Wq[(d + 3) * 256 + j], Wk[(d + 3) * 256 + i], a3);
        }
        g_Wqk[j * 256 + i] = (a0 + a1 + a2 + a3) * SCALE_;
    } else if (blockIdx.x == 256) {
        float a = 0.f;
        #pragma unroll 4
        for (int d = 0; d < 256; d++) a = fmaf(bq[d], Wk[d * 256 + i], a);
        g_bqk[i] = a * SCALE_;
    } else if (blockIdx.x == 257) {
        float a = 0.f;
        #pragma unroll 4
        for (int d = 0; d < 256; d++) a = fmaf(Wq[d * 256 + i], bk[d], a);
        g_wb[i] = a * SCALE_;
    } else {
        float a = bq[i] * bk[i], dm = 0.f;
        blockReduce2(a, dm);
        if (i == 0) g_c0 = a * SCALE_;
    }
}

// =================== kSlotA: LN(slots) + qt GEMV + gq/C1/C2 + zero P/SA/SW ===================
// grid 128, block 256. 4 rows per block.
__global__ void __launch_bounds__(256) kSlotA(const float* __restrict__ ls_g, const float* __restrict__ ls_b,
                                              const float* __restrict__ gg, const float* __restrict__ gb) {
    __shared__ float s_sn[4][256];
    int j = threadIdx.x;
    int r0 = blockIdx.x * 4;
    #pragma unroll
    for (int r = 0; r < 4; r++) {
        int row = r0 + r;
        float v = g_slots[(size_t)row * 256 + j];
        float a = v, b = v * v;
        blockReduce2(a, b);
        float m = a * (1.0f / 256.0f);
        float var = b * (1.0f / 256.0f) - m * m;
        float rs = rsqrtf(var + EPSLN);
        s_sn[r][j] = (v - m) * rs * ls_g[j] + ls_b[j];
    }
    __syncthreads();
    float acc[4] = {0.f, 0.f, 0.f, 0.f};
    #pragma unroll 4
    for (int i = 0; i < 256; i++) {
        float w = g_Wqk[i * 256 + j];
        #pragma unroll
        for (int r = 0; r < 4; r++) acc[r] = fmaf(s_sn[r][i], w, acc[r]);
    }
    float bqk = g_bqk[j], wbj = g_wb[j], ggj = gg[j], gbj = gb[j], c0 = g_c0;
    #pragma unroll
    for (int r = 0; r < 4; r++) {
        int row = r0 + r;
        float qt = acc[r] + bqk;
        float gq = ggj * qt;
        g_gq[(size_t)row * 256 + j] = gq;
        float c1 = gq;
        float c2 = qt * gbj + s_sn[r][j] * wbj;
        blockReduce2(c1, c2);
        if (j == 0) { g_C1[row] = c1; g_C2[row] = c2 + c0; }
        g_P[(size_t)row * 256 + j] = 0.f;
        if (j == 0) { g_SA[row] = 0.f; g_SW[row] = 0.f; }
    }
}

// ============ FUSED: LN + dots + softmax + P/SA/SW accumulation ============
// grid (16, 64), block 128 (4 warps). Each warp: 64 consecutive rows.
__global__ void __launch_bounds__(128) kFA(const float* __restrict__ inputs,
                                           int last, float* __restrict__ out_attn) {
    int b = blockIdx.y;
    int warp = threadIdx.x >> 5, lane = threadIdx.x & 31;
    int row0 = blockIdx.x * 256 + warp * 64;
    int r8 = b * 8;

    u64 gq[8][4];
    float C1[8], C2[8];
    #pragma unroll
    for (int k = 0; k < 8; k++) {
        const float* gp = g_gq + (size_t)(r8 + k) * 256;
        float2 q0 = *(const float2*)(gp + 4 * lane);
        float2 q1 = *(const float2*)(gp + 4 * lane + 2);
        float2 q2 = *(const float2*)(gp + 128 + 4 * lane);
        float2 q3 = *(const float2*)(gp + 128 + 4 * lane + 2);
        gq[k][0] = pk2(q0.x, q0.y); gq[k][1] = pk2(q1.x, q1.y);
        gq[k][2] = pk2(q2.x, q2.y); gq[k][3] = pk2(q3.x, q3.y);
        C1[k] = g_C1[r8 + k]; C2[k] = g_C2[r8 + k];
    }
    u64 zero2 = pk2(0.f, 0.f);
    u64 P[8][4];
    #pragma unroll
    for (int k = 0; k < 8; k++) { P[k][0] = zero2; P[k][1] = zero2; P[k][2] = zero2; P[k][3] = zero2; }
    float SA[8] = {0.f, 0.f, 0.f, 0.f, 0.f, 0.f, 0.f, 0.f};
    float SW[8] = {0.f, 0.f, 0.f, 0.f, 0.f, 0.f, 0.f, 0.f};

    const float4* vp = (const float4*)(inputs + ((size_t)b * N_ + row0) * 256);
    float4 a0 = vp[lane], a1 = vp[lane + 32];

    for (int r = 0; r < 64; r++) {
        int n = row0 + r;
        float4 b0, b1;
        if (r < 63) {
            const float4* vn = vp + (size_t)(r + 1) * 64;
            b0 = vn[lane]; b1 = vn[lane + 32];
        }
        float s  = ((a0.x + a0.y) + (a0.z + a0.w)) + ((a1.x + a1.y) + (a1.z + a1.w));
        float ss = fmaf(a0.x, a0.x, fmaf(a0.y, a0.y, fmaf(a0.z, a0.z, fmaf(a0.w, a0.w,
                   fmaf(a1.x, a1.x, fmaf(a1.y, a1.y, fmaf(a1.z, a1.z, a1.w * a1.w)))))));
        #pragma unroll
        for (int o = 16; o; o >>= 1) {
            s  += __shfl_xor_sync(0xffffffffu, s, o);
            ss += __shfl_xor_sync(0xffffffffu, ss, o);
        }
        float m  = s * (1.0f / 256.0f);
        float var = fmaf(ss, 1.0f / 256.0f, -m * m);
        float rs = rsqrtf(var + EPSLN);
        float w  = m * rs;

        u64 x01 = pk2(a0.x, a0.y), x23 = pk2(a0.z, a0.w);
        u64 x45 = pk2(a1.x, a1.y), x67 = pk2(a1.z, a1.w);

        float dt[8];
        #pragma unroll
        for (int k = 0; k < 8; k++) {
            u64 d2 = zero2;
            fma2(d2, x01, gq[k][0]); fma2(d2, x23, gq[k][1]);
            fma2(d2, x45, gq[k][2]); fma2(d2, x67, gq[k][3]);
            float lo, hi; upk2(d2, lo, hi);
            dt[k] = lo + hi;
        }
        #pragma unroll
        for (int o = 16; o; o >>= 1)
            #pragma unroll
            for (int k = 0; k < 8; k++) dt[k] += __shfl_xor_sync(0xffffffffu, dt[k], o);

        float lg[8];
        #pragma unroll
        for (int k = 0; k < 8; k++) lg[k] = fmaf(rs, dt[k], fmaf(-w, C1[k], C2[k]));
        float mx = lg[0];
        #pragma unroll
        for (int k = 1; k < 8; k++) mx = fmaxf(mx, lg[k]);
        float ak[8], esum = 0.f;
        #pragma unroll
        for (int k = 0; k < 8; k++) { ak[k] = __expf(lg[k] - mx); esum += ak[k]; }
        float inv = __fdividef(1.0f, esum);
        #pragma unroll
        for (int k = 0; k < 8; k++) ak[k] *= inv;

        if (last) {
            #pragma unroll
            for (int k = 0; k < 8; k++)
                if (lane == k) out_attn[(size_t)(r8 + k) * N_ + n] = ak[k];
        }

        #pragma unroll
        for (int k = 0; k < 8; k++) {
            float ar = ak[k] * rs;
            u64 ap = pk2(ar, ar);
            fma2(P[k][0], ap, x01); fma2(P[k][1], ap, x23);
            fma2(P[k][2], ap, x45); fma2(P[k][3], ap, x67);
            SA[k] += ak[k];
            SW[k] = fmaf(ak[k], w, SW[k]);
        }
        a0 = b0; a1 = b1;
    }

    // flush: block-level smem reduction, then 1/4 the atomics
    __shared__ float sP[4][8][256];     // 32 KB
    __shared__ float sSA[4][8], sSW[4][8];
    #pragma unroll
    for (int k = 0; k < 8; k++) {
        float x, y;
        upk2(P[k][0], x, y); sP[warp][k][4 * lane] = x;       sP[warp][k][4 * lane + 1] = y;
        upk2(P[k][1], x, y); sP[warp][k][4 * lane + 2] = x;   sP[warp][k][4 * lane + 3] = y;
        upk2(P[k][2], x, y); sP[warp][k][128 + 4 * lane] = x; sP[warp][k][128 + 4 * lane + 1] = y;
        upk2(P[k][3], x, y); sP[warp][k][128 + 4 * lane + 2] = x; sP[warp][k][128 + 4 * lane + 3] = y;
    }
    if (lane == 0) {
        #pragma unroll
        for (int k = 0; k < 8; k++) { sSA[warp][k] = SA[k]; sSW[warp][k] = SW[k]; }
    }
    __syncthreads();
    for (int t = threadIdx.x; t < 2048; t += 128) {
        int k = t >> 8, d = t & 255;
        float v = (sP[0][k][d] + sP[1][k][d]) + (sP[2][k][d] + sP[3][k][d]);
        atomicAdd(&g_P[(size_t)(r8 + k) * 256 + d], v);
    }
    if (threadIdx.x < 8) {
        int k = threadIdx.x;
        atomicAdd(&g_SA[r8 + k], (sSA[0][k] + sSA[1][k]) + (sSA[2][k] + sSA[3][k]));
    } else if (threadIdx.x < 16) {
        int k = threadIdx.x - 8;
        atomicAdd(&g_SW[r8 + k], (sSW[0][k] + sSW[1][k]) + (sSW[2][k] + sSW[3][k]));
    }
}

// =================== kSlotB: un -> updates -> GRU -> LN -> FF -> slots ===================
// grid 128, block 256, 4 rows per block.
__global__ void __launch_bounds__(256) kSlotB(const float* __restrict__ gg, const float* __restrict__ gb,
                                              const float* __restrict__ bv,
                                              const float* __restrict__ b_ih, const float* __restrict__ b_hh,
                                              const float* __restrict__ lnf_g, const float* __restrict__ lnf_b,
                                              const float* __restrict__ b1, const float* __restrict__ b2,
                                              int last, float* __restrict__ out_slots) {
    __shared__ float s_un[4][256];
    __shared__ float s_x[4][256];
    __shared__ float s_sl[4][256];
    __shared__ float s_ff[4][256];
    __shared__ float s_f1[4][512];
    int j = threadIdx.x;
    int r0 = blockIdx.x * 4;
    float snorm[4];

    // stage 1: un
    float ggj = gg[j], gbj = gb[j];
    #pragma unroll
    for (int r = 0; r < 4; r++) {
        int row = r0 + r;
        float SA = g_SA[row], SW = g_SW[row];
        float inv = 1.0f / (SA + EPSA);
        float Pv = g_P[(size_t)row * 256 + j];
        s_un[r][j] = (ggj * (Pv - SW) + gbj * SA) * inv;
        s_sl[r][j] = g_slots[(size_t)row * 256 + j];
        snorm[r] = SA * inv;
    }
    __syncthreads();

    // stage 2: updates = un @ WvT + snorm*bv
    {
        float acc[4] = {0.f, 0.f, 0.f, 0.f};
        #pragma unroll 4
        for (int i = 0; i < 256; i++) {
            float w = g_WvT[i * 256 + j];
            #pragma unroll
            for (int r = 0; r < 4; r++) acc[r] = fmaf(s_un[r][i], w, acc[r]);
        }
        float bvj = bv[j];
        #pragma unroll
        for (int r = 0; r < 4; r++) s_x[r][j] = acc[r] + snorm[r] * bvj;
    }
    __syncthreads();

    // stage 3: GRU gates (6 GEMVs fused) + combine + ln_ff
    float h_reg[4];
    {
        float air[4] = {}, aiz[4] = {}, ain[4] = {}, ahr[4] = {}, ahz[4] = {}, ahn[4] = {};
        #pragma unroll 2
        for (int i = 0; i < 256; i++) {
            float wr = g_WihT[i * 768 + j];
            float wz = g_WihT[i * 768 + 256 + j];
            float wn = g_WihT[i * 768 + 512 + j];
            float vr = g_WhhT[i * 768 + j];
            float vz = g_WhhT[i * 768 + 256 + j];
            float vn = g_WhhT[i * 768 + 512 + j];
            #pragma unroll
            for (int r = 0; r < 4; r++) {
                float xr = s_x[r][i], sl = s_sl[r][i];
                air[r] = fmaf(xr, wr, air[r]); aiz[r] = fmaf(xr, wz, aiz[r]); ain[r] = fmaf(xr, wn, ain[r]);
                ahr[r] = fmaf(sl, vr, ahr[r]); ahz[r] = fmaf(sl, vz, ahz[r]); ahn[r] = fmaf(sl, vn, ahn[r]);
            }
        }
        float bir = b_ih[j], biz = b_ih[256 + j], bin = b_ih[512 + j];
        float bhr = b_hh[j], bhz = b_hh[256 + j], bhn = b_hh[512 + j];
        float lgj = lnf_g[j], lbj = lnf_b[j];
        #pragma unroll
        for (int r = 0; r < 4; r++) {
            float rr = 1.0f / (1.0f + __expf(-(air[r] + bir + ahr[r] + bhr)));
            float zz = 1.0f / (1.0f + __expf(-(aiz[r] + biz + ahz[r] + bhz)));
            float nn = tanhf(ain[r] + bin + rr * (ahn[r] + bhn));
            float h = (1.0f - zz) * nn + zz * s_sl[r][j];
            h_reg[r] = h;
            float a = h, b = h * h;
            blockReduce2(a, b);
            float m = a * (1.0f / 256.0f);
            float var = b * (1.0f / 256.0f) - m * m;
            float rs = rsqrtf(var + EPSLN);
            s_ff[r][j] = (h - m) * rs * lgj + lbj;
        }
    }
    __syncthreads();

    // stage 5: f1 = relu(ff @ W1T + b1), 512 outputs -> 2 per thread
    {
        float f0[4] = {}, f1v[4] = {};
        #pragma unroll 2
        for (int i = 0; i < 256; i++) {
            float w0 = g_W1T[i * 512 + j];
            float w1 = g_W1T[i * 512 + 256 + j];
            #pragma unroll
            for (int r = 0; r < 4; r++) {
                float a = s_ff[r][i];
                f0[r] = fmaf(a, w0, f0[r]);
                f1v[r] = fmaf(a, w1, f1v[r]);
            }
        }
        float b1a = b1[j], b1b = b1[256 + j];
        #pragma unroll
        for (int r = 0; r < 4; r++) {
            s_f1[r][j] = fmaxf(f0[r] + b1a, 0.f);
            s_f1[r][j + 256] = fmaxf(f1v[r] + b1b, 0.f);
        }
    }
    __syncthreads();

    // stage 6: slots = h + f1 @ W2T + b2
    {
        float o[4] = {};
        #pragma unroll 4
        for (int i = 0; i < 512; i++) {
            float w = g_W2T[i * 256 + j];
            #pragma unroll
            for (int r = 0; r < 4; r++) o[r] = fmaf(s_f1[r][i], w, o[r]);
        }
        float b2j = b2[j];
        #pragma unroll
        for (int r = 0; r < 4; r++) {
            int row = r0 + r;
            float v = h_reg[r] + o[r] + b2j;
            g_slots[(size_t)row * 256 + j] = v;
            if (last) out_slots[(size_t)row * 256 + j] = v;
        }
    }
}

// ---------------- launch ----------------
extern "C" void kernel_launch(void* const* d_in, const int* in_sizes, int n_in,
                              void* d_out, int out_size) {
    (void)in_sizes; (void)n_in; (void)out_size;
    const float* inputs  = (const float*)d_in[0];
    const float* noise   = (const float*)d_in[1];
    const float* slot_mu = (const float*)d_in[2];
    const float* slot_ls = (const float*)d_in[3];
    const float* Wq      = (const float*)d_in[4];
    const float* bq      = (const float*)d_in[5];
    const float* Wk      = (const float*)d_in[6];
    const float* bk      = (const float*)d_in[7];
    const float* Wv      = (const float*)d_in[8];
    const float* bv      = (const float*)d_in[9];
    const float* W_ih    = (const float*)d_in[10];
    const float* b_ih    = (const float*)d_in[11];
    const float* W_hh    = (const float*)d_in[12];
    const float* b_hh    = (const float*)d_in[13];
    const float* ln_in_g = (const float*)d_in[14];
    const float* ln_in_b = (const float*)d_in[15];
    const float* ln_s_g  = (const float*)d_in[16];
    const float* ln_s_b  = (const float*)d_in[17];
    const float* ln_ff_g = (const float*)d_in[18];
    const float* ln_ff_b = (const float*)d_in[19];
    const float* W1      = (const float*)d_in[20];
    const float* b1      = (const float*)d_in[21];
    const float* W2      = (const float*)d_in[22];
    const float* b2      = (const float*)d_in[23];

    float* out = (float*)d_out;
    float* out_slots = out;
    float* out_attn  = out + BK_ * D_;

    // prep: 2 launches
    kSetup<<<1216, 256>>>(W_ih, W_hh, Wv, W1, W2, noise, slot_mu, slot_ls);
    kWqkAll<<<259, 256>>>(Wq, Wk, bq, bk);

    // 3 iterations x 3 launches
    for (int it = 0; it < 3; it++) {
        int last = (it == 2);
        kSlotA<<<128, 256>>>(ln_s_g, ln_s_b, ln_in_g, ln_in_b);
        kFA<<<dim3(16, 64), 128>>>(inputs, last, out_attn);
        kSlotB<<<128, 256>>>(ln_in_g, ln_in_b, bv, b_ih, b_hh,
                             ln_ff_g, ln_ff_b, b1, b2, last, last ? out_slots : out_slots);
    }
}

// round 7
// speedup vs baseline: 1.3248x; 1.3248x over previous
#include <cuda_runtime.h>
#include <math.h>
#include <stdint.h>
#include <stddef.h>

// ---------------- problem dims ----------------
#define B_    64
#define N_    4096
#define DIN_  256
#define K_    8
#define D_    256
#define H_    512
#define BK_   512
#define SCALE_ 0.0625f
#define EPSLN 1e-5f
#define EPSA  1e-8f

typedef unsigned long long u64;

// ---------------- device scratch ----------------
__device__ __align__(16) float g_slots[BK_ * D_];
__device__ __align__(16) float g_gq[BK_ * D_];      // g ⊙ qt
__device__ float g_C1[BK_];
__device__ float g_C2[BK_];
__device__ __align__(16) float g_P[BK_ * D_];       // Σ a*rs*v
__device__ float g_SA[BK_];
__device__ float g_SW[BK_];
__device__ __align__(16) float g_Wqk[D_ * D_];
__device__ float g_bqk[D_];
__device__ float g_wb[D_];
__device__ float g_c0;
__device__ __align__(16) float g_WihT[D_ * 3 * D_];
__device__ __align__(16) float g_WhhT[D_ * 3 * D_];
__device__ __align__(16) float g_WvT[D_ * D_];
__device__ __align__(16) float g_W1T[D_ * H_];
__device__ __align__(16) float g_W2T[H_ * D_];

// ---------------- f32x2 packed helpers ----------------
__device__ __forceinline__ u64 pk2(float x, float y) {
    u64 r; asm("mov.b64 %0, {%1, %2};" : "=l"(r) : "f"(x), "f"(y)); return r;
}
__device__ __forceinline__ void upk2(u64 v, float& x, float& y) {
    asm("mov.b64 {%0, %1}, %2;" : "=f"(x), "=f"(y) : "l"(v));
}
__device__ __forceinline__ void fma2(u64& d, u64 a, u64 b) {
    asm("fma.rn.f32x2 %0, %1, %2, %0;" : "+l"(d) : "l"(a), "l"(b));
}

// ---------------- block reduce (2 values, 256 threads) ----------------
__device__ __forceinline__ void blockReduce2(float& a, float& b) {
    #pragma unroll
    for (int o = 16; o; o >>= 1) {
        a += __shfl_xor_sync(0xffffffffu, a, o);
        b += __shfl_xor_sync(0xffffffffu, b, o);
    }
    __shared__ float sa[8], sb[8];
    __syncthreads();
    int w = threadIdx.x >> 5;
    if ((threadIdx.x & 31) == 0) { sa[w] = a; sb[w] = b; }
    __syncthreads();
    a = sa[threadIdx.x & 7];
    b = sb[threadIdx.x & 7];
    #pragma unroll
    for (int o = 4; o; o >>= 1) {
        a += __shfl_xor_sync(0xffffffffu, a, o);
        b += __shfl_xor_sync(0xffffffffu, b, o);
    }
}

// ---------------- smem-tiled GEMV: acc[r] += s_in[r][k] * W[k][col_off+j] ----------------
// TK=16, tile = 16x256 floats (16KB). 256 threads, j = threadIdx.x. Block-uniform.
__device__ __forceinline__ void gemvTile(const float* __restrict__ W, int rstride, int col_off, int K,
                                         const float* s_in, int in_stride,
                                         float* sTile, int j, float acc[4]) {
    for (int k0 = 0; k0 < K; k0 += 16) {
        __syncthreads();
        #pragma unroll
        for (int e = 0; e < 4; e++) {
            int idx = e * 256 + j;      // [0,1024) float4s
            int row = idx >> 6;         // 64 float4 per 256-float row
            int c   = idx & 63;
            ((float4*)sTile)[idx] =
                ((const float4*)(W + (size_t)(k0 + row) * rstride + col_off))[c];
        }
        __syncthreads();
        #pragma unroll
        for (int kk = 0; kk < 16; kk++) {
            float w = sTile[kk * 256 + j];
            #pragma unroll
            for (int r = 0; r < 4; r++)
                acc[r] = fmaf(s_in[r * in_stride + k0 + kk], w, acc[r]);
        }
    }
}

// ---------------- slot-A body: qt GEMV + gq/C1/C2 + zero P/SA/SW ----------------
__device__ __forceinline__ void slotABody(const float (*s_sn)[256], float* sTile, int r0, int j,
                                          const float* __restrict__ gg, const float* __restrict__ gb) {
    float acc[4] = {0.f, 0.f, 0.f, 0.f};
    gemvTile(g_Wqk, 256, 0, 256, &s_sn[0][0], 256, sTile, j, acc);
    float bqk = g_bqk[j], wbj = g_wb[j], ggj = gg[j], gbj = gb[j], c0 = g_c0;
    #pragma unroll
    for (int r = 0; r < 4; r++) {
        int row = r0 + r;
        float qt = acc[r] + bqk;
        float gq = ggj * qt;
        g_gq[(size_t)row * 256 + j] = gq;
        float c1 = gq;
        float c2 = fmaf(qt, gbj, s_sn[r][j] * wbj);
        blockReduce2(c1, c2);
        if (j == 0) { g_C1[row] = c1; g_C2[row] = c2 + c0; }
        g_P[(size_t)row * 256 + j] = 0.f;
        if (j == 0) { g_SA[row] = 0.f; g_SW[row] = 0.f; }
    }
}

// =================== SETUP: transposes + slot init + Wqk/bqk/wb/c0, ONE launch ===================
__device__ __forceinline__ void tTile(const float* __restrict__ src, float* __restrict__ dst,
                                      int R, int C, int bx, int by) {
    __shared__ float t[32][33];
    int tx = threadIdx.x & 31, ty = threadIdx.x >> 5;
    int c = bx * 32 + tx;
    int r = by * 32 + ty;
    #pragma unroll
    for (int k = 0; k < 32; k += 8)
        t[ty + k][tx] = src[(size_t)(r + k) * C + c];
    __syncthreads();
    int cc = bx * 32 + ty;
    int rr = by * 32 + tx;
    #pragma unroll
    for (int k = 0; k < 32; k += 8)
        dst[(size_t)(cc + k) * R + rr] = t[tx][ty + k];
}

__global__ void __launch_bounds__(256) kSetup(const float* __restrict__ W_ih, const float* __restrict__ W_hh,
                                              const float* __restrict__ Wv, const float* __restrict__ W1,
                                              const float* __restrict__ W2, const float* __restrict__ noise,
                                              const float* __restrict__ mu, const float* __restrict__ ls,
                                              const float* __restrict__ Wq, const float* __restrict__ Wk,
                                              const float* __restrict__ bq, const float* __restrict__ bk) {
    int t = blockIdx.x;
    int i = threadIdx.x;
    if (t < 192)       tTile(W_ih, g_WihT, 768, 256, t & 7, t >> 3);
    else if (t < 384)  { int u = t - 192; tTile(W_hh, g_WhhT, 768, 256, u & 7, u >> 3); }
    else if (t < 448)  { int u = t - 384; tTile(Wv,   g_WvT,  256, 256, u & 7, u >> 3); }
    else if (t < 576)  { int u = t - 448; tTile(W1,   g_W1T,  512, 256, u & 7, u >> 3); }
    else if (t < 704)  { int u = t - 576; tTile(W2,   g_W2T,  256, 512, u & 15, u >> 4); }
    else if (t < 1216) {
        int idx = (t - 704) * 256 + i;
        int d = idx & 255;
        g_slots[idx] = mu[d] + __expf(ls[d]) * noise[idx];
    } else if (t < 1472) {
        int jj = t - 1216;
        float acc[8] = {0.f,0.f,0.f,0.f,0.f,0.f,0.f,0.f};
        #pragma unroll 4
        for (int d = 0; d < 256; d += 8) {
            #pragma unroll
            for (int u = 0; u < 8; u++)
                acc[u] = fmaf(Wq[(d + u) * 256 + jj], Wk[(d + u) * 256 + i], acc[u]);
        }
        g_Wqk[jj * 256 + i] =
            (((acc[0] + acc[1]) + (acc[2] + acc[3])) + ((acc[4] + acc[5]) + (acc[6] + acc[7]))) * SCALE_;
    } else if (t == 1472) {
        float a = 0.f;
        #pragma unroll 8
        for (int d = 0; d < 256; d++) a = fmaf(bq[d], Wk[d * 256 + i], a);
        g_bqk[i] = a * SCALE_;
    } else if (t == 1473) {
        float a = 0.f;
        #pragma unroll 8
        for (int d = 0; d < 256; d++) a = fmaf(Wq[d * 256 + i], bk[d], a);
        g_wb[i] = a * SCALE_;
    } else {
        float a = bq[i] * bk[i], dm = 0.f;
        blockReduce2(a, dm);
        if (i == 0) g_c0 = a * SCALE_;
    }
}

// =================== kSlotA (iteration 0 only) ===================
__global__ void __launch_bounds__(256) kSlotA(const float* __restrict__ ls_g, const float* __restrict__ ls_b,
                                              const float* __restrict__ gg, const float* __restrict__ gb) {
    __shared__ float s_sn[4][256];
    __shared__ float sTile[4096];   // 16KB
    int j = threadIdx.x;
    int r0 = blockIdx.x * 4;
    float lsg = ls_g[j], lsb = ls_b[j];
    #pragma unroll
    for (int r = 0; r < 4; r++) {
        float v = g_slots[(size_t)(r0 + r) * 256 + j];
        float a = v, b = v * v;
        blockReduce2(a, b);
        float m = a * (1.0f / 256.0f);
        float var = b * (1.0f / 256.0f) - m * m;
        float rs = rsqrtf(var + EPSLN);
        s_sn[r][j] = (v - m) * rs * lsg + lsb;
    }
    __syncthreads();
    slotABody(s_sn, sTile, r0, j, gg, gb);
}

// ============ kFA: LN + dots + softmax + P/SA/SW accumulation (distributed reductions) ============
// grid (16, 64), block 128 (4 warps), each warp 64 rows.
__global__ void __launch_bounds__(128) kFA(const float* __restrict__ inputs,
                                           int last, float* __restrict__ out_attn) {
    int b = blockIdx.y;
    int warp = threadIdx.x >> 5, lane = threadIdx.x & 31;
    int row0 = blockIdx.x * 256 + warp * 64;
    int r8 = b * 8;
    // bit-reversal slot owned by this lane after distributed reduction
    int slane = ((lane & 1) << 2) | (lane & 2) | ((lane >> 2) & 1);

    u64 gq[8][4];
    #pragma unroll
    for (int k = 0; k < 8; k++) {
        const float* gp = g_gq + (size_t)(r8 + k) * 256;
        float2 q0 = *(const float2*)(gp + 4 * lane);
        float2 q1 = *(const float2*)(gp + 4 * lane + 2);
        float2 q2 = *(const float2*)(gp + 128 + 4 * lane);
        float2 q3 = *(const float2*)(gp + 128 + 4 * lane + 2);
        gq[k][0] = pk2(q0.x, q0.y); gq[k][1] = pk2(q1.x, q1.y);
        gq[k][2] = pk2(q2.x, q2.y); gq[k][3] = pk2(q3.x, q3.y);
    }
    float C1s = g_C1[r8 + slane], C2s = g_C2[r8 + slane];

    u64 zero2 = pk2(0.f, 0.f);
    u64 P[8][4];
    #pragma unroll
    for (int k = 0; k < 8; k++) { P[k][0] = zero2; P[k][1] = zero2; P[k][2] = zero2; P[k][3] = zero2; }
    float SAl = 0.f, SWl = 0.f;

    const float4* vp = (const float4*)(inputs + ((size_t)b * N_ + row0) * 256);
    float4 a0 = vp[lane], a1 = vp[lane + 32];

    for (int r = 0; r < 64; r++) {
        int n = row0 + r;
        float4 b0v, b1v;
        if (r < 63) {
            const float4* vn = vp + (size_t)(r + 1) * 64;
            b0v = vn[lane]; b1v = vn[lane + 32];
        }
        // LN stats (distributed 6-shfl reduce + broadcast)
        float s  = ((a0.x + a0.y) + (a0.z + a0.w)) + ((a1.x + a1.y) + (a1.z + a1.w));
        float ss = fmaf(a0.x, a0.x, fmaf(a0.y, a0.y, fmaf(a0.z, a0.z, fmaf(a0.w, a0.w,
                   fmaf(a1.x, a1.x, fmaf(a1.y, a1.y, fmaf(a1.z, a1.z, a1.w * a1.w)))))));
        {
            bool odd = lane & 1;
            float send = odd ? s : ss;
            float rcv = __shfl_xor_sync(0xffffffffu, send, 1);
            float v = odd ? (ss + rcv) : (s + rcv);
            v += __shfl_xor_sync(0xffffffffu, v, 2);
            v += __shfl_xor_sync(0xffffffffu, v, 4);
            v += __shfl_xor_sync(0xffffffffu, v, 8);
            v += __shfl_xor_sync(0xffffffffu, v, 16);
            float o = __shfl_xor_sync(0xffffffffu, v, 1);
            s  = odd ? o : v;
            ss = odd ? v : o;
        }
        float m   = s * (1.0f / 256.0f);
        float var = fmaf(ss, 1.0f / 256.0f, -m * m);
        float rs  = rsqrtf(var + EPSLN);
        float w   = m * rs;

        u64 x01 = pk2(a0.x, a0.y), x23 = pk2(a0.z, a0.w);
        u64 x45 = pk2(a1.x, a1.y), x67 = pk2(a1.z, a1.w);

        // dots (packed)
        float dt[8];
        #pragma unroll
        for (int k = 0; k < 8; k++) {
            u64 d2 = zero2;
            fma2(d2, x01, gq[k][0]); fma2(d2, x23, gq[k][1]);
            fma2(d2, x45, gq[k][2]); fma2(d2, x67, gq[k][3]);
            float lo, hi; upk2(d2, lo, hi);
            dt[k] = lo + hi;
        }
        // distributed 8-value butterfly reduce (9 shfl): lane ends with slot slane total
        float vdot;
        {
            bool c0 = lane & 1;
            float t0 = c0 ? dt[0] : dt[4];
            float t1 = c0 ? dt[1] : dt[5];
            float t2 = c0 ? dt[2] : dt[6];
            float t3 = c0 ? dt[3] : dt[7];
            t0 = __shfl_xor_sync(0xffffffffu, t0, 1);
            t1 = __shfl_xor_sync(0xffffffffu, t1, 1);
            t2 = __shfl_xor_sync(0xffffffffu, t2, 1);
            t3 = __shfl_xor_sync(0xffffffffu, t3, 1);
            float u0 = (c0 ? dt[4] : dt[0]) + t0;
            float u1 = (c0 ? dt[5] : dt[1]) + t1;
            float u2 = (c0 ? dt[6] : dt[2]) + t2;
            float u3 = (c0 ? dt[7] : dt[3]) + t3;
            bool c1 = lane & 2;
            float s0 = c1 ? u0 : u2;
            float s1 = c1 ? u1 : u3;
            s0 = __shfl_xor_sync(0xffffffffu, s0, 2);
            s1 = __shfl_xor_sync(0xffffffffu, s1, 2);
            float w0 = (c1 ? u2 : u0) + s0;
            float w1 = (c1 ? u3 : u1) + s1;
            bool c2 = lane & 4;
            float s2 = c2 ? w0 : w1;
            s2 = __shfl_xor_sync(0xffffffffu, s2, 4);
            vdot = (c2 ? w1 : w0) + s2;
            vdot += __shfl_xor_sync(0xffffffffu, vdot, 8);
            vdot += __shfl_xor_sync(0xffffffffu, vdot, 16);
        }
        // distributed softmax (lane owns slot slane)
        float lg = fmaf(rs, vdot, fmaf(-w, C1s, C2s));
        float mx = lg;
        mx = fmaxf(mx, __shfl_xor_sync(0xffffffffu, mx, 1));
        mx = fmaxf(mx, __shfl_xor_sync(0xffffffffu, mx, 2));
        mx = fmaxf(mx, __shfl_xor_sync(0xffffffffu, mx, 4));
        float e = __expf(lg - mx);
        float sm = e;
        sm += __shfl_xor_sync(0xffffffffu, sm, 1);
        sm += __shfl_xor_sync(0xffffffffu, sm, 2);
        sm += __shfl_xor_sync(0xffffffffu, sm, 4);
        float a = __fdividef(e, sm);
        SAl += a;
        SWl = fmaf(a, w, SWl);
        if (last && lane < 8)
            out_attn[(size_t)(r8 + slane) * N_ + n] = a;

        // broadcast all 8 attention weights (slot k lives at group lane s(k))
        int gbase = lane & 24;
        float ak[8];
        ak[0] = __shfl_sync(0xffffffffu, a, gbase | 0);
        ak[1] = __shfl_sync(0xffffffffu, a, gbase | 4);
        ak[2] = __shfl_sync(0xffffffffu, a, gbase | 2);
        ak[3] = __shfl_sync(0xffffffffu, a, gbase | 6);
        ak[4] = __shfl_sync(0xffffffffu, a, gbase | 1);
        ak[5] = __shfl_sync(0xffffffffu, a, gbase | 5);
        ak[6] = __shfl_sync(0xffffffffu, a, gbase | 3);
        ak[7] = __shfl_sync(0xffffffffu, a, gbase | 7);

        #pragma unroll
        for (int k = 0; k < 8; k++) {
            float ar = ak[k] * rs;
            u64 ap = pk2(ar, ar);
            fma2(P[k][0], ap, x01); fma2(P[k][1], ap, x23);
            fma2(P[k][2], ap, x45); fma2(P[k][3], ap, x67);
        }
        a0 = b0v; a1 = b1v;
    }

    // flush: block-level smem reduction, then atomics
    __shared__ float sP[4][8][256];
    __shared__ float sSA[4][8], sSW[4][8];
    #pragma unroll
    for (int k = 0; k < 8; k++) {
        float x, y;
        upk2(P[k][0], x, y); sP[warp][k][4 * lane] = x;       sP[warp][k][4 * lane + 1] = y;
        upk2(P[k][1], x, y); sP[warp][k][4 * lane + 2] = x;   sP[warp][k][4 * lane + 3] = y;
        upk2(P[k][2], x, y); sP[warp][k][128 + 4 * lane] = x; sP[warp][k][128 + 4 * lane + 1] = y;
        upk2(P[k][3], x, y); sP[warp][k][128 + 4 * lane + 2] = x; sP[warp][k][128 + 4 * lane + 3] = y;
    }
    if (lane < 8) { sSA[warp][slane] = SAl; sSW[warp][slane] = SWl; }
    __syncthreads();
    for (int t = threadIdx.x; t < 2048; t += 128) {
        int k = t >> 8, d = t & 255;
        float v = (sP[0][k][d] + sP[1][k][d]) + (sP[2][k][d] + sP[3][k][d]);
        atomicAdd(&g_P[(size_t)(r8 + k) * 256 + d], v);
    }
    if (threadIdx.x < 8) {
        int k = threadIdx.x;
        atomicAdd(&g_SA[r8 + k], (sSA[0][k] + sSA[1][k]) + (sSA[2][k] + sSA[3][k]));
    } else if (threadIdx.x < 16) {
        int k = threadIdx.x - 8;
        atomicAdd(&g_SW[r8 + k], (sSW[0][k] + sSW[1][k]) + (sSW[2][k] + sSW[3][k]));
    }
}

// =================== kSlotB: un -> updates -> GRU -> LN -> FF -> slots (+ fused next slotA) ===================
// grid 128, block 256, 4 rows per block. All GEMV stages smem-tiled.
__global__ void __launch_bounds__(256) kSlotB(const float* __restrict__ gg, const float* __restrict__ gb,
                                              const float* __restrict__ bv,
                                              const float* __restrict__ b_ih, const float* __restrict__ b_hh,
                                              const float* __restrict__ lnf_g, const float* __restrict__ lnf_b,
                                              const float* __restrict__ b1, const float* __restrict__ b2,
                                              const float* __restrict__ ls_g, const float* __restrict__ ls_b,
                                              int last, float* __restrict__ out_slots) {
    __shared__ float sA[4][256];    // un -> ff
    __shared__ float sB[4][256];    // updates(x) -> sn
    __shared__ float sSL[4][256];   // prev slots
    __shared__ float sF1[4][512];
    __shared__ float sTile[4096];   // 16KB weight tile
    int j = threadIdx.x;
    int r0 = blockIdx.x * 4;
    float snorm[4];

    // stage 1: un & slots
    float ggj = gg[j], gbj = gb[j];
    #pragma unroll
    for (int r = 0; r < 4; r++) {
        int row = r0 + r;
        float SA = g_SA[row], SW = g_SW[row];
        float inv = 1.0f / (SA + EPSA);
        float Pv = g_P[(size_t)row * 256 + j];
        sA[r][j] = (ggj * (Pv - SW) + gbj * SA) * inv;
        sSL[r][j] = g_slots[(size_t)row * 256 + j];
        snorm[r] = SA * inv;
    }
    __syncthreads();

    // stage 2: x = un @ WvT + snorm*bv
    {
        float acc[4] = {0.f, 0.f, 0.f, 0.f};
        gemvTile(g_WvT, 256, 0, 256, &sA[0][0], 256, sTile, j, acc);
        float bvj = bv[j];
        #pragma unroll
        for (int r = 0; r < 4; r++) sB[r][j] = fmaf(snorm[r], bvj, acc[r]);
    }
    __syncthreads();

    // stage 3: GRU gates (6 tiled GEMVs)
    float air[4] = {}, aiz[4] = {}, ain[4] = {}, ahr[4] = {}, ahz[4] = {}, ahn[4] = {};
    gemvTile(g_WihT, 768, 0,   256, &sB[0][0],  256, sTile, j, air);
    gemvTile(g_WihT, 768, 256, 256, &sB[0][0],  256, sTile, j, aiz);
    gemvTile(g_WihT, 768, 512, 256, &sB[0][0],  256, sTile, j, ain);
    gemvTile(g_WhhT, 768, 0,   256, &sSL[0][0], 256, sTile, j, ahr);
    gemvTile(g_WhhT, 768, 256, 256, &sSL[0][0], 256, sTile, j, ahz);
    gemvTile(g_WhhT, 768, 512, 256, &sSL[0][0], 256, sTile, j, ahn);

    // stage 4: GRU combine + ln_ff (ff -> sA)
    float h_reg[4];
    {
        float bir = b_ih[j], biz = b_ih[256 + j], bin = b_ih[512 + j];
        float bhr = b_hh[j], bhz = b_hh[256 + j], bhn = b_hh[512 + j];
        float lgj = lnf_g[j], lbj = lnf_b[j];
        __syncthreads();
        #pragma unroll
        for (int r = 0; r < 4; r++) {
            float rr = 1.0f / (1.0f + __expf(-(air[r] + bir + ahr[r] + bhr)));
            float zz = 1.0f / (1.0f + __expf(-(aiz[r] + biz + ahz[r] + bhz)));
            float nn = tanhf(ain[r] + bin + rr * (ahn[r] + bhn));
            float h = (1.0f - zz) * nn + zz * sSL[r][j];
            h_reg[r] = h;
            float a = h, bb = h * h;
            blockReduce2(a, bb);
            float m = a * (1.0f / 256.0f);
            float var = bb * (1.0f / 256.0f) - m * m;
            float rs = rsqrtf(var + EPSLN);
            sA[r][j] = (h - m) * rs * lgj + lbj;
        }
    }
    __syncthreads();

    // stage 5: f1 = relu(ff @ W1T + b1)
    {
        float f0[4] = {}, f1v[4] = {};
        gemvTile(g_W1T, 512, 0,   256, &sA[0][0], 256, sTile, j, f0);
        gemvTile(g_W1T, 512, 256, 256, &sA[0][0], 256, sTile, j, f1v);
        float b1a = b1[j], b1b = b1[256 + j];
        __syncthreads();
        #pragma unroll
        for (int r = 0; r < 4; r++) {
            sF1[r][j]       = fmaxf(f0[r]  + b1a, 0.f);
            sF1[r][256 + j] = fmaxf(f1v[r] + b1b, 0.f);
        }
    }
    __syncthreads();

    // stage 6: new slots = h + f1 @ W2T + b2
    float ns[4];
    {
        float o[4] = {};
        gemvTile(g_W2T, 256, 0, 512, &sF1[0][0], 512, sTile, j, o);
        float b2j = b2[j];
        #pragma unroll
        for (int r = 0; r < 4; r++) {
            ns[r] = h_reg[r] + o[r] + b2j;
            g_slots[(size_t)(r0 + r) * 256 + j] = ns[r];
            if (last) out_slots[(size_t)(r0 + r) * 256 + j] = ns[r];
        }
    }

    // fused next-iteration slotA (skip on last iter)
    if (!last) {
        float lsg = ls_g[j], lsb = ls_b[j];
        #pragma unroll
        for (int r = 0; r < 4; r++) {
            float v = ns[r];
            float a = v, bb = v * v;
            blockReduce2(a, bb);
            float m = a * (1.0f / 256.0f);
            float var = bb * (1.0f / 256.0f) - m * m;
            float rs = rsqrtf(var + EPSLN);
            sB[r][j] = (v - m) * rs * lsg + lsb;
        }
        __syncthreads();
        slotABody(sB, sTile, r0, j, gg, gb);
    }
}

// ---------------- launch ----------------
extern "C" void kernel_launch(void* const* d_in, const int* in_sizes, int n_in,
                              void* d_out, int out_size) {
    (void)in_sizes; (void)n_in; (void)out_size;
    const float* inputs  = (const float*)d_in[0];
    const float* noise   = (const float*)d_in[1];
    const float* slot_mu = (const float*)d_in[2];
    const float* slot_ls = (const float*)d_in[3];
    const float* Wq      = (const float*)d_in[4];
    const float* bq      = (const float*)d_in[5];
    const float* Wk      = (const float*)d_in[6];
    const float* bk      = (const float*)d_in[7];
    const float* Wv      = (const float*)d_in[8];
    const float* bv      = (const float*)d_in[9];
    const float* W_ih    = (const float*)d_in[10];
    const float* b_ih    = (const float*)d_in[11];
    const float* W_hh    = (const float*)d_in[12];
    const float* b_hh    = (const float*)d_in[13];
    const float* ln_in_g = (const float*)d_in[14];
    const float* ln_in_b = (const float*)d_in[15];
    const float* ln_s_g  = (const float*)d_in[16];
    const float* ln_s_b  = (const float*)d_in[17];
    const float* ln_ff_g = (const float*)d_in[18];
    const float* ln_ff_b = (const float*)d_in[19];
    const float* W1      = (const float*)d_in[20];
    const float* b1      = (const float*)d_in[21];
    const float* W2      = (const float*)d_in[22];
    const float* b2      = (const float*)d_in[23];

    float* out = (float*)d_out;
    float* out_slots = out;
    float* out_attn  = out + BK_ * D_;

    // prep: 1 launch (transposes + slot init + folded attention constants)
    kSetup<<<1475, 256>>>(W_ih, W_hh, Wv, W1, W2, noise, slot_mu, slot_ls, Wq, Wk, bq, bk);
    // iter-0 slot A
    kSlotA<<<128, 256>>>(ln_s_g, ln_s_b, ln_in_g, ln_in_b);

    // 3 iterations x 2 launches
    for (int it = 0; it < 3; it++) {
        int last = (it == 2);
        kFA<<<dim3(16, 64), 128>>>(inputs, last, out_attn);
        kSlotB<<<128, 256>>>(ln_in_g, ln_in_b, bv, b_ih, b_hh,
                             ln_ff_g, ln_ff_b, b1, b2, ln_s_g, ln_s_b,
                             last, out_slots);
    }
}